// round 14
// baseline (speedup 1.0000x reference)
#include <cuda_runtime.h>
#include <cuda_fp16.h>
#include <cstdint>

#define HW 36864
#define Cc 256
#define ATTN_ELEMS 75497472   // 1152*16*64*64
#define AVG_ELEMS  73728      // 1152*64

// W as fp16 A-fragments: [ot(4)][chunk(8)][s(2)][mt(8)][lane(32)] x uint4
__device__ __align__(16) uint4 g_wfrag[16384];

__device__ __forceinline__ float ex2f(float x) {
    float y;
    asm("ex2.approx.ftz.f32 %0, %1;" : "=f"(y) : "f"(x));
    return y;
}
__device__ __forceinline__ void mma_f16(float c[4], const uint32_t a[4], const uint32_t b[2]) {
    asm volatile(
        "mma.sync.aligned.m16n8k16.row.col.f32.f16.f16.f32 "
        "{%0,%1,%2,%3}, {%4,%5,%6,%7}, {%8,%9}, {%0,%1,%2,%3};"
        : "+f"(c[0]), "+f"(c[1]), "+f"(c[2]), "+f"(c[3])
        : "r"(a[0]), "r"(a[1]), "r"(a[2]), "r"(a[3]), "r"(b[0]), "r"(b[1]));
}

// ---------------- one-time W -> fp16 A-fragment image (verified R12/R13) ---------------
__global__ __launch_bounds__(256) void wconv_kernel(const float* __restrict__ w) {
    int t = blockIdx.x * 256 + threadIdx.x;      // 0..16383
    int lane = t & 31;
    int grp  = t >> 5;                           // [ot][c][s][mt]
    int mt = grp & 7, s = (grp >> 3) & 1, c = (grp >> 4) & 7, ot = grp >> 7;
    int r0 = ot * 128 + mt * 16 + (lane >> 2);
    int k0 = c * 32 + s * 16 + 2 * (lane & 3);
    const float* wr = w + r0 * Cc;
    __half2 h0 = __floats2half2_rn(wr[k0],              wr[k0 + 1]);
    __half2 h1 = __floats2half2_rn(wr[8 * Cc + k0],     wr[8 * Cc + k0 + 1]);
    __half2 h2 = __floats2half2_rn(wr[k0 + 8],          wr[k0 + 9]);
    __half2 h3 = __floats2half2_rn(wr[8 * Cc + k0 + 8], wr[8 * Cc + k0 + 9]);
    uint4 v;
    v.x = *reinterpret_cast<uint32_t*>(&h0);
    v.y = *reinterpret_cast<uint32_t*>(&h1);
    v.z = *reinterpret_cast<uint32_t*>(&h2);
    v.w = *reinterpret_cast<uint32_t*>(&h3);
    g_wfrag[t] = v;
}

// smem map (bytes), NON-overlapping:
//   [0, 73728)        qk: q [16][64][18] halves (36864) then k (36864)
//   [73728, 108544)   Bh2 [128][68] half2 (34816)
//   [108544, 110592)  sinv[512]
//   [110592, 112640)  sbz[512]
//   [112640, 112896)  savg[64]
#define QK_OFF   0
#define BH_OFF   73728
#define SINV_OFF 108544
#define SBZ_OFF  110592
#define SAVG_OFF 112640
#define FUSED_SMEM 112896

__global__ __launch_bounds__(256, 2) void fused_kernel(
    const float* __restrict__ x, const float* __restrict__ rel_table,
    const float* __restrict__ gamma, const float* __restrict__ beta,
    const float* __restrict__ rmean, const float* __restrict__ rvar,
    float* __restrict__ out_attn, float* __restrict__ out_avg)
{
    extern __shared__ __align__(16) char dsm[];
    __half* qkh = reinterpret_cast<__half*>(dsm + QK_OFF);
    __half2 (*Bh2)[68] = reinterpret_cast<__half2(*)[68]>(dsm + BH_OFF);
    float* sinv = reinterpret_cast<float*>(dsm + SINV_OFF);
    float* sbz  = reinterpret_cast<float*>(dsm + SBZ_OFF);
    float* savg = reinterpret_cast<float*>(dsm + SAVG_OFF);

    const int tid  = threadIdx.x;
    const int w    = tid >> 5;
    const int lane = tid & 31;
    const int g    = lane >> 2;
    const int l3   = lane & 3;

    const int win = blockIdx.x;
    const int b   = win / 576;
    const int wrr = (win - b * 576) / 24;
    const int wcc = win - b * 576 - wrr * 24;
    const float* xw = x + (size_t)b * (Cc * HW) + (wrr * 8) * 192 + wcc * 8;

    // ---- phase 1: BN params, avg init, X -> Bh2 (half2 pixel-pairs per k-pair) ----
#pragma unroll
    for (int i = 0; i < 2; i++) {
        int o = tid + i * 256;
        float iv = gamma[o] * rsqrtf(rvar[o] + 1e-5f);
        sinv[o] = iv;
        sbz[o]  = beta[o] - rmean[o] * iv;
    }
    if (tid < 64) savg[tid] = 0.f;
    {
        int n2 = lane * 2;                   // pixel pair
        int r = n2 >> 3, c0 = n2 & 7;
        const float* xp = xw + r * 192 + c0;
#pragma unroll
        for (int i = 0; i < 16; i++) {
            int kp = w * 16 + i;             // k-pair 0..127
            const float* p0 = xp + (size_t)(2 * kp) * HW;
            float2 fa = *reinterpret_cast<const float2*>(p0);
            float2 fb = *reinterpret_cast<const float2*>(p0 + HW);
            __half2 h0 = __floats2half2_rn(fa.x, fb.x);
            __half2 h1 = __floats2half2_rn(fa.y, fb.y);
            uint2 v = { *reinterpret_cast<uint32_t*>(&h0), *reinterpret_cast<uint32_t*>(&h1) };
            *reinterpret_cast<uint2*>(&Bh2[kp][n2]) = v;
        }
    }
    __syncthreads();

    // ---- phase 2+3: GEMM in two 32-row halves + epilogue into qk smem ----
#pragma unroll 1
    for (int hh = 0; hh < 2; hh++) {
        const int mb  = 4 * w + 2 * hh;      // 16-row tile index base (0..31)
        const int ot  = mb >> 3;
        const int mtb = mb & 7;

        float acc[2][8][4];
#pragma unroll
        for (int mi = 0; mi < 2; mi++)
#pragma unroll
            for (int ni = 0; ni < 8; ni++)
#pragma unroll
                for (int r = 0; r < 4; r++) acc[mi][ni][r] = 0.f;

#pragma unroll
        for (int c = 0; c < 8; c++) {
#pragma unroll
            for (int s = 0; s < 2; s++) {
                const uint4* wf = &g_wfrag[(((ot * 8 + c) * 2 + s) * 8 + mtb) * 32 + lane];
                uint4 a0v = wf[0];
                uint4 a1v = wf[32];
                uint32_t a0[4] = {a0v.x, a0v.y, a0v.z, a0v.w};
                uint32_t a1[4] = {a1v.x, a1v.y, a1v.z, a1v.w};
                const int kpb = c * 16 + s * 8;
#pragma unroll
                for (int ni = 0; ni < 8; ni++) {
                    int col = ni * 8 + g;
                    uint32_t bf[2];
                    bf[0] = *reinterpret_cast<const uint32_t*>(&Bh2[kpb + l3][col]);
                    bf[1] = *reinterpret_cast<const uint32_t*>(&Bh2[kpb + l3 + 4][col]);
                    mma_f16(acc[0][ni], a0, bf);
                    mma_f16(acc[1][ni], a1, bf);
                }
            }
        }

        // epilogue: BN + ReLU (+ q log2-scale) -> qk smem [qkv][head][n][18] halves
#pragma unroll
        for (int mi = 0; mi < 2; mi++) {
            const int hd16 = mb + mi;            // 0..31
            const int qkv  = hd16 >> 4;
            const int head = hd16 & 15;
            const float qm = (qkv == 0) ? 0.36067376f : 1.0f;  // 0.25*log2(e) into q
            __half* reg = qkh + qkv * 18432 + head * 1152;
#pragma unroll
            for (int rh = 0; rh < 2; rh++) {
                const int d = g + 8 * rh;
                const int o = hd16 * 16 + d;
                const float iv = sinv[o], bz = sbz[o];
                __half* hb = reg + d;
#pragma unroll
                for (int ni = 0; ni < 8; ni++)
#pragma unroll
                    for (int e = 0; e < 2; e++) {
                        float t = acc[mi][ni][2 * rh + e] * iv + bz;
                        t = t > 0.f ? t * qm : 0.f;
                        int n = ni * 8 + 2 * l3 + e;
                        hb[n * 18] = __float2half_rn(t);
                    }
            }
        }
    }
    __syncthreads();

    // ---- phase 4: attention — warp w handles heads 2w, 2w+1 ----
    const int X0 = g - 2 * l3 + 7;
#pragma unroll 1
    for (int hd2 = 0; hd2 < 2; hd2++) {
        const int head = 2 * w + hd2;
        const __half* qh = qkh + head * 1152;
        const __half* kh = qkh + 18432 + head * 1152;

#pragma unroll 1
        for (int slice = 0; slice < 4; slice++) {
            const int row = slice * 16 + g;
            uint32_t a[4];
            a[0] = *reinterpret_cast<const uint32_t*>(&qh[row * 18 + 2 * l3]);
            a[1] = *reinterpret_cast<const uint32_t*>(&qh[(row + 8) * 18 + 2 * l3]);
            a[2] = *reinterpret_cast<const uint32_t*>(&qh[row * 18 + 2 * l3 + 8]);
            a[3] = *reinterpret_cast<const uint32_t*>(&qh[(row + 8) * 18 + 2 * l3 + 8]);

            float dac[8][4];
#pragma unroll
            for (int ni = 0; ni < 8; ni++) {
#pragma unroll
                for (int r = 0; r < 4; r++) dac[ni][r] = 0.f;
                int col = ni * 8 + g;
                uint32_t bf[2];
                bf[0] = *reinterpret_cast<const uint32_t*>(&kh[col * 18 + 2 * l3]);
                bf[1] = *reinterpret_cast<const uint32_t*>(&kh[col * 18 + 2 * l3 + 8]);
                mma_f16(dac[ni], a, bf);
            }

            // bias from rel_table (L1-resident), scaled by log2(e)
#pragma unroll
            for (int ni = 0; ni < 8; ni++) {
                const int rb = (slice * 2 - ni + 7) * 15;
                dac[ni][0] += __ldg(&rel_table[(rb + X0)     * 16 + head]) * 1.4426950408f;
                dac[ni][1] += __ldg(&rel_table[(rb + X0 - 1) * 16 + head]) * 1.4426950408f;
                dac[ni][2] += __ldg(&rel_table[(rb + 15 + X0)     * 16 + head]) * 1.4426950408f;
                dac[ni][3] += __ldg(&rel_table[(rb + 15 + X0 - 1) * 16 + head]) * 1.4426950408f;
            }

            // avg column sums (pre-softmax, x = x' * ln2) -> smem
#pragma unroll
            for (int ni = 0; ni < 8; ni++)
#pragma unroll
                for (int e = 0; e < 2; e++) {
                    float s = dac[ni][e] + dac[ni][2 + e];
                    s += __shfl_xor_sync(0xffffffffu, s, 4);
                    s += __shfl_xor_sync(0xffffffffu, s, 8);
                    s += __shfl_xor_sync(0xffffffffu, s, 16);
                    if (g == 0)
                        atomicAdd(&savg[ni * 8 + 2 * l3 + e], s * 6.7690154e-4f); // ln2/1024
                }

            // row softmax in log2 domain
#pragma unroll
            for (int h = 0; h < 2; h++) {
                float mx = fmaxf(dac[0][2*h], dac[0][2*h+1]);
#pragma unroll
                for (int ni = 1; ni < 8; ni++)
                    mx = fmaxf(mx, fmaxf(dac[ni][2*h], dac[ni][2*h+1]));
                mx = fmaxf(mx, __shfl_xor_sync(0xffffffffu, mx, 1));
                mx = fmaxf(mx, __shfl_xor_sync(0xffffffffu, mx, 2));
                float sum = 0.f;
#pragma unroll
                for (int ni = 0; ni < 8; ni++) {
                    dac[ni][2*h]   = ex2f(dac[ni][2*h]   - mx);
                    dac[ni][2*h+1] = ex2f(dac[ni][2*h+1] - mx);
                    sum += dac[ni][2*h] + dac[ni][2*h+1];
                }
                sum += __shfl_xor_sync(0xffffffffu, sum, 1);
                sum += __shfl_xor_sync(0xffffffffu, sum, 2);
                float rinv = __frcp_rn(sum);
#pragma unroll
                for (int ni = 0; ni < 8; ni++) {
                    dac[ni][2*h]   *= rinv;
                    dac[ni][2*h+1] *= rinv;
                }
            }

            float* ob = out_attn
                      + ((size_t)(win * 16 + head) * 64 + slice * 16 + g) * 64 + 2 * l3;
#pragma unroll
            for (int ni = 0; ni < 8; ni++) {
                *reinterpret_cast<float2*>(ob + ni * 8) =
                    make_float2(dac[ni][0], dac[ni][1]);
                *reinterpret_cast<float2*>(ob + 8 * 64 + ni * 8) =
                    make_float2(dac[ni][2], dac[ni][3]);
            }
        }
    }
    __syncthreads();
    if (tid < 64) out_avg[win * 64 + tid] = savg[tid];
}

extern "C" void kernel_launch(void* const* d_in, const int* in_sizes, int n_in,
                              void* d_out, int out_size) {
    const float* x     = (const float*)d_in[0];
    const float* w     = (const float*)d_in[1];
    const float* gamma = (const float*)d_in[2];
    const float* beta  = (const float*)d_in[3];
    const float* rmean = (const float*)d_in[4];
    const float* rvar  = (const float*)d_in[5];
    const float* rel   = (const float*)d_in[6];
    float* out     = (float*)d_out;
    float* out_avg = out + ATTN_ELEMS;

    static bool attr_set = false;
    if (!attr_set) {
        cudaFuncSetAttribute(fused_kernel, cudaFuncAttributeMaxDynamicSharedMemorySize,
                             FUSED_SMEM);
        attr_set = true;
    }
    wconv_kernel<<<64, 256>>>(w);
    fused_kernel<<<1152, 256, FUSED_SMEM>>>(x, rel, gamma, beta, rmean, rvar, out, out_avg);
}

// round 15
// speedup vs baseline: 1.1872x; 1.1872x over previous
#include <cuda_runtime.h>
#include <cuda_fp16.h>
#include <cstdint>

#define HW 36864
#define Cc 256
#define QKV_STRIDE 18874368   // halves: 1152*16*64*16
#define ATTN_ELEMS 75497472   // 1152*16*64*64
#define AVG_ELEMS  73728      // 1152*64

// fp16 fragment scratch (j-split layout):
// q: [win*16+head][slice(4)][j(4)][attn_lane(32)][2] halves   (j = rowbit + 2*khalf)
// k: [win*16+head][ni(8)][khalf(2)][attn_lane(32)][2] halves
__device__ __align__(16) __half g_scratch[2 * QKV_STRIDE];

__device__ __forceinline__ float ex2f(float x) {
    float y;
    asm("ex2.approx.ftz.f32 %0, %1;" : "=f"(y) : "f"(x));
    return y;
}
__device__ __forceinline__ uint32_t smem_u32(const void* p) {
    uint32_t a;
    asm("{ .reg .u64 t; cvta.to.shared.u64 t, %1; cvt.u32.u64 %0, t; }" : "=r"(a) : "l"(p));
    return a;
}
__device__ __forceinline__ void mma_f16(float c[4], const uint32_t a[4], const uint32_t b[2]) {
    asm volatile(
        "mma.sync.aligned.m16n8k16.row.col.f32.f16.f16.f32 "
        "{%0,%1,%2,%3}, {%4,%5,%6,%7}, {%8,%9}, {%0,%1,%2,%3};"
        : "+f"(c[0]), "+f"(c[1]), "+f"(c[2]), "+f"(c[3])
        : "r"(a[0]), "r"(a[1]), "r"(a[2]), "r"(a[3]), "r"(b[0]), "r"(b[1]));
}
#define CP_ASYNC16(d, s) \
    asm volatile("cp.async.cg.shared.global [%0], [%1], 16;" :: "r"(d), "l"(s) : "memory")
#define CP_COMMIT()  asm volatile("cp.async.commit_group;" ::: "memory")
#define CP_WAIT0()   asm volatile("cp.async.wait_group 0;" ::: "memory")

#define BS_BYTES 33792          // [2][32][132] floats (cp.async landing)
#define PROJ_SMEM (BS_BYTES + 1024)

// ---------------- fused 1x1conv (fp16 HMMA, cp.async) + BN + ReLU + j-split scatter ----
// C[o,p] = sum_c W[o,c] * X[b,c,p]   M=512(o) N=73728(p) K=256
// Block 128x128, 8 warps (2x4), warp 64x32 = 4x4 m16n8k16 frags, K-chunk 32, 8 chunks.
__global__ __launch_bounds__(256, 2) void proj_kernel(
    const float* __restrict__ x, const float* __restrict__ w,
    const float* __restrict__ gamma, const float* __restrict__ beta,
    const float* __restrict__ rmean, const float* __restrict__ rvar)
{
    extern __shared__ __align__(16) char dsm[];
    float (*Bs)[32][132] = reinterpret_cast<float(*)[32][132]>(dsm);
    float* sinv = reinterpret_cast<float*>(dsm + BS_BYTES);
    float* sbz  = sinv + 128;
    __shared__ __align__(16) __half As[2][128][40];   // [buf][o][k] halves (bank-clean)

    const int tid  = threadIdx.x;
    const int warp = tid >> 5;
    const int lane = tid & 31;
    const int o0   = blockIdx.x * 128;
    const int pg0  = blockIdx.y * 128;
    const int b    = pg0 / HW;               // tile never crosses batch
    const int pp0  = pg0 - b * HW;
    const float* xb = x + (size_t)b * (Cc * HW);

    if (tid < 128) {
        int og = o0 + tid;
        float iv = gamma[og] * rsqrtf(rvar[og] + 1e-5f);
        sinv[tid] = iv;
        sbz[tid]  = beta[og] - rmean[og] * iv;
    }

    const int g  = lane >> 2;
    const int l3 = lane & 3;
    const int wm = (warp >> 2) * 64;
    const int wn = (warp & 3) * 32;

    const uint32_t bs0 = smem_u32(&Bs[0][0][0]);
    #define ISSUE_B(cc, buf) do {                                                  \
        const float* _src = xb + (size_t)((cc) * 32) * HW + pp0;                   \
        _Pragma("unroll")                                                          \
        for (int l = 0; l < 4; l++) {                                              \
            int idx = tid + l * 256;                                               \
            int r = idx >> 5, c16 = idx & 31;                                      \
            uint32_t d = bs0 + (buf) * (32*132*4) + r * 528 + c16 * 16;            \
            CP_ASYNC16(d, _src + (size_t)r * HW + c16 * 4);                        \
        }                                                                          \
        CP_COMMIT();                                                               \
    } while (0)

    float acc[4][4][4];
#pragma unroll
    for (int mi = 0; mi < 4; mi++)
#pragma unroll
        for (int ni = 0; ni < 4; ni++)
#pragma unroll
            for (int r = 0; r < 4; r++) acc[mi][ni][r] = 0.f;

    ISSUE_B(0, 0);

#pragma unroll 1
    for (int c = 0; c < 8; c++) {
        const int bufo = c & 1;
        float4 ra[4];
#pragma unroll
        for (int l = 0; l < 4; l++) {
            int idx = tid + l * 256;
            int oo = idx >> 3, kq = idx & 7;
            ra[l] = *reinterpret_cast<const float4*>(&w[(o0 + oo) * Cc + c * 32 + kq * 4]);
        }
        CP_WAIT0();
        __syncthreads();
        if (c + 1 < 8) ISSUE_B(c + 1, bufo ^ 1);
#pragma unroll
        for (int l = 0; l < 4; l++) {
            int idx = tid + l * 256;
            int oo = idx >> 3, kq = idx & 7;
            __half2 hp[2] = { __floats2half2_rn(ra[l].x, ra[l].y),
                              __floats2half2_rn(ra[l].z, ra[l].w) };
            *reinterpret_cast<uint2*>(&As[bufo][oo][kq * 4]) = *reinterpret_cast<uint2*>(hp);
        }
        __syncthreads();

#pragma unroll
        for (int s = 0; s < 2; s++) {
            const int k = s * 16 + 2 * l3;
            uint32_t a[4][4], bf[4][2];
#pragma unroll
            for (int mi = 0; mi < 4; mi++) {
                int m = wm + mi * 16 + g;
                a[mi][0] = *reinterpret_cast<const uint32_t*>(&As[bufo][m][k]);
                a[mi][1] = *reinterpret_cast<const uint32_t*>(&As[bufo][m + 8][k]);
                a[mi][2] = *reinterpret_cast<const uint32_t*>(&As[bufo][m][k + 8]);
                a[mi][3] = *reinterpret_cast<const uint32_t*>(&As[bufo][m + 8][k + 8]);
            }
#pragma unroll
            for (int ni = 0; ni < 4; ni++) {
                int p = wn + ni * 8 + g;
                __half2 h0 = __floats2half2_rn(Bs[bufo][k][p],     Bs[bufo][k + 1][p]);
                __half2 h1 = __floats2half2_rn(Bs[bufo][k + 8][p], Bs[bufo][k + 9][p]);
                bf[ni][0] = *reinterpret_cast<uint32_t*>(&h0);
                bf[ni][1] = *reinterpret_cast<uint32_t*>(&h1);
            }
#pragma unroll
            for (int mi = 0; mi < 4; mi++)
#pragma unroll
                for (int ni = 0; ni < 4; ni++)
                    mma_f16(acc[mi][ni], a[mi], bf[ni]);
        }
    }
    #undef ISSUE_B

    // epilogue: BN + ReLU + scatter into j-split fragment layouts
    int winv[4][2], nn[4][2];
#pragma unroll
    for (int ni = 0; ni < 4; ni++)
#pragma unroll
        for (int e = 0; e < 2; e++) {
            int pin = pp0 + wn + ni * 8 + 2 * l3 + e;
            int row = pin / 192;
            int col = pin - row * 192;
            winv[ni][e] = b * 576 + (row >> 3) * 24 + (col >> 3);
            nn[ni][e]   = ((row & 7) << 3) + (col & 7);
        }
#pragma unroll
    for (int mi = 0; mi < 4; mi++) {
#pragma unroll
        for (int rh = 0; rh < 2; rh++) {
            int ol = wm + mi * 16 + g + rh * 8;
            int o  = o0 + ol;
            float iv = sinv[ol], bz = sbz[ol];
            int qkv  = o >> 8;
            int head = (o >> 4) & 15;
            int d    = o & 15;
            int dl = (d >> 1) & 3, de = d & 1, dh = d >> 3;
            __half* gb = g_scratch + (size_t)qkv * QKV_STRIDE + head * 1024;
#pragma unroll
            for (int ni = 0; ni < 4; ni++)
#pragma unroll
                for (int e = 0; e < 2; e++) {
                    float t = acc[mi][ni][rh * 2 + e] * iv + bz;
                    t = t > 0.f ? t : 0.f;
                    int n = nn[ni][e];
                    int off;
                    if (qkv == 0) {
                        t *= 0.36067376f;   // 0.25 * log2(e) folded into q
                        // q: slice*256 + (rowbit + 2*khalf)*64 + attn_lane*2 + de
                        off = (n >> 4) * 256 + (((n >> 3) & 1) + 2 * dh) * 64
                            + ((((n & 7) << 2) | dl) << 1) + de;
                    } else {
                        // k: ni*128 + khalf*64 + attn_lane*2 + de
                        off = (n >> 3) * 128 + dh * 64
                            + ((((n & 7) << 2) | dl) << 1) + de;
                    }
                    gb[(size_t)winv[ni][e] * 16384 + off] = __float2half_rn(t);
                }
        }
    }
}

// ---------------- attention: j-split frag loads (dense 128B lines), log2 softmax -------
__global__ __launch_bounds__(256, 4) void attn_kernel(
    const float* __restrict__ rel_table,
    float* __restrict__ out_attn, float* __restrict__ out_avg)
{
    __shared__ float biasl[232];

    const int tid  = threadIdx.x;
    const int w    = tid >> 5;
    const int lane = tid & 31;
    const int head = blockIdx.x & 15;
    const int wp   = blockIdx.x >> 4;

    if (tid < 225) biasl[tid] = rel_table[tid * 16 + head] * 1.4426950408f;
    __syncthreads();

    const int win   = wp * 2 + (w >> 2);
    const int slice = w & 3;
    const __half* qb = g_scratch + (size_t)(win * 16 + head) * 1024;
    const __half* kb = qb + QKV_STRIDE;

    // A fragment: 4 x LDG.32, each instruction a dense 128B line
    const __half* qs = qb + slice * 256;
    uint32_t a[4];
    a[0] = *reinterpret_cast<const uint32_t*>(qs + 0 * 64 + lane * 2);
    a[1] = *reinterpret_cast<const uint32_t*>(qs + 1 * 64 + lane * 2);
    a[2] = *reinterpret_cast<const uint32_t*>(qs + 2 * 64 + lane * 2);
    a[3] = *reinterpret_cast<const uint32_t*>(qs + 3 * 64 + lane * 2);

    float acc[8][4];
#pragma unroll
    for (int ni = 0; ni < 8; ni++) {
#pragma unroll
        for (int r = 0; r < 4; r++) acc[ni][r] = 0.f;
        uint32_t bf[2];
        bf[0] = *reinterpret_cast<const uint32_t*>(kb + ni * 128 + lane * 2);
        bf[1] = *reinterpret_cast<const uint32_t*>(kb + ni * 128 + 64 + lane * 2);
        mma_f16(acc[ni], a, bf);
    }

    const int g  = lane >> 2;
    const int l3 = lane & 3;
    const int X0 = g - 2 * l3 + 7;
#pragma unroll
    for (int ni = 0; ni < 8; ni++) {
        const float* r0 = &biasl[(slice * 2 - ni + 7) * 15];
        acc[ni][0] += r0[X0];
        acc[ni][1] += r0[X0 - 1];
        acc[ni][2] += r0[15 + X0];
        acc[ni][3] += r0[15 + X0 - 1];
    }

#pragma unroll
    for (int ni = 0; ni < 8; ni++)
#pragma unroll
        for (int e = 0; e < 2; e++) {
            float s = acc[ni][e] + acc[ni][2 + e];
            s += __shfl_xor_sync(0xffffffffu, s, 4);
            s += __shfl_xor_sync(0xffffffffu, s, 8);
            s += __shfl_xor_sync(0xffffffffu, s, 16);
            if (g == 0)
                atomicAdd(&out_avg[win * 64 + ni * 8 + 2 * l3 + e],
                          s * 6.7690154e-4f);   // ln2/1024
        }

#pragma unroll
    for (int h = 0; h < 2; h++) {
        float mx = fmaxf(acc[0][2*h], acc[0][2*h+1]);
#pragma unroll
        for (int ni = 1; ni < 8; ni++)
            mx = fmaxf(mx, fmaxf(acc[ni][2*h], acc[ni][2*h+1]));
        mx = fmaxf(mx, __shfl_xor_sync(0xffffffffu, mx, 1));
        mx = fmaxf(mx, __shfl_xor_sync(0xffffffffu, mx, 2));
        float sum = 0.f;
#pragma unroll
        for (int ni = 0; ni < 8; ni++) {
            acc[ni][2*h]   = ex2f(acc[ni][2*h]   - mx);
            acc[ni][2*h+1] = ex2f(acc[ni][2*h+1] - mx);
            sum += acc[ni][2*h] + acc[ni][2*h+1];
        }
        sum += __shfl_xor_sync(0xffffffffu, sum, 1);
        sum += __shfl_xor_sync(0xffffffffu, sum, 2);
        float rinv = __frcp_rn(sum);
#pragma unroll
        for (int ni = 0; ni < 8; ni++) {
            acc[ni][2*h]   *= rinv;
            acc[ni][2*h+1] *= rinv;
        }
    }

    float* ob = out_attn + ((size_t)(win * 16 + head) * 64 + slice * 16 + g) * 64 + 2 * l3;
#pragma unroll
    for (int ni = 0; ni < 8; ni++) {
        *reinterpret_cast<float2*>(ob + ni * 8)          = make_float2(acc[ni][0], acc[ni][1]);
        *reinterpret_cast<float2*>(ob + 8 * 64 + ni * 8) = make_float2(acc[ni][2], acc[ni][3]);
    }
}

extern "C" void kernel_launch(void* const* d_in, const int* in_sizes, int n_in,
                              void* d_out, int out_size) {
    const float* x     = (const float*)d_in[0];
    const float* w     = (const float*)d_in[1];
    const float* gamma = (const float*)d_in[2];
    const float* beta  = (const float*)d_in[3];
    const float* rmean = (const float*)d_in[4];
    const float* rvar  = (const float*)d_in[5];
    const float* rel   = (const float*)d_in[6];
    float* out     = (float*)d_out;
    float* out_avg = out + ATTN_ELEMS;

    static bool attr_set = false;
    if (!attr_set) {
        cudaFuncSetAttribute(proj_kernel, cudaFuncAttributeMaxDynamicSharedMemorySize,
                             PROJ_SMEM);
        attr_set = true;
    }
    cudaMemsetAsync(out_avg, 0, AVG_ELEMS * sizeof(float));
    proj_kernel<<<dim3(4, 576), 256, PROJ_SMEM>>>(x, w, gamma, beta, rmean, rvar);
    attn_kernel<<<9216, 256>>>(rel, out, out_avg);
}

// round 16
// speedup vs baseline: 1.2454x; 1.0490x over previous
#include <cuda_runtime.h>
#include <cuda_fp16.h>
#include <cstdint>

#define HW 36864
#define Cc 256
#define QKV_STRIDE 18874368   // halves: 1152*16*64*16
#define ATTN_ELEMS 75497472   // 1152*16*64*64
#define AVG_ELEMS  73728      // 1152*64

// fp16 fragment scratch (j-split layout):
// q: [win*16+head][slice(4)][j(4)][attn_lane(32)][2] halves   (j = rowbit + 2*khalf)
// k: [win*16+head][ni(8)][khalf(2)][attn_lane(32)][2] halves
__device__ __align__(16) __half g_scratch[2 * QKV_STRIDE];

// W as fp16 A-fragments: [ot(4)][kstep(16)][mt(8)][lane(32)] x uint4
__device__ __align__(16) uint4 g_wfrag[16384];

__device__ __forceinline__ float ex2f(float x) {
    float y;
    asm("ex2.approx.ftz.f32 %0, %1;" : "=f"(y) : "f"(x));
    return y;
}
__device__ __forceinline__ uint32_t smem_u32(const void* p) {
    uint32_t a;
    asm("{ .reg .u64 t; cvta.to.shared.u64 t, %1; cvt.u32.u64 %0, t; }" : "=r"(a) : "l"(p));
    return a;
}
__device__ __forceinline__ void mma_f16(float c[4], const uint32_t a[4], const uint32_t b[2]) {
    asm volatile(
        "mma.sync.aligned.m16n8k16.row.col.f32.f16.f16.f32 "
        "{%0,%1,%2,%3}, {%4,%5,%6,%7}, {%8,%9}, {%0,%1,%2,%3};"
        : "+f"(c[0]), "+f"(c[1]), "+f"(c[2]), "+f"(c[3])
        : "r"(a[0]), "r"(a[1]), "r"(a[2]), "r"(a[3]), "r"(b[0]), "r"(b[1]));
}
#define CP_ASYNC16(d, s) \
    asm volatile("cp.async.cg.shared.global [%0], [%1], 16;" :: "r"(d), "l"(s) : "memory")
#define CP_COMMIT()  asm volatile("cp.async.commit_group;" ::: "memory")
#define CP_WAIT0()   asm volatile("cp.async.wait_group 0;" ::: "memory")

#define BS_STRIDE 33792         // bytes per B buffer: [64][132] floats
#define PROJ_SMEM (2 * BS_STRIDE + 1024)

// ---------------- one-time W -> fp16 A-fragment image (verified R12/R13) ---------------
__global__ __launch_bounds__(256) void wconv_kernel(const float* __restrict__ w) {
    int t = blockIdx.x * 256 + threadIdx.x;      // 0..16383
    int lane = t & 31;
    int grp  = t >> 5;                           // [ot][kstep16][mt]
    int mt = grp & 7, ks = (grp >> 3) & 15, ot = grp >> 7;
    int r0 = ot * 128 + mt * 16 + (lane >> 2);
    int k0 = ks * 16 + 2 * (lane & 3);
    const float* wr = w + r0 * Cc;
    __half2 h0 = __floats2half2_rn(wr[k0],              wr[k0 + 1]);
    __half2 h1 = __floats2half2_rn(wr[8 * Cc + k0],     wr[8 * Cc + k0 + 1]);
    __half2 h2 = __floats2half2_rn(wr[k0 + 8],          wr[k0 + 9]);
    __half2 h3 = __floats2half2_rn(wr[8 * Cc + k0 + 8], wr[8 * Cc + k0 + 9]);
    uint4 v;
    v.x = *reinterpret_cast<uint32_t*>(&h0);
    v.y = *reinterpret_cast<uint32_t*>(&h1);
    v.z = *reinterpret_cast<uint32_t*>(&h2);
    v.w = *reinterpret_cast<uint32_t*>(&h3);
    g_wfrag[t] = v;
}

// ---------------- fused 1x1conv (fp16 HMMA, K-chunk 64, 1 barrier/chunk) ---------------
// C[o,p] = sum_c W[o,c] * X[b,c,p]   M=512(o) N=73728(p) K=256
// Block 128x128, 8 warps (2x4), warp 64x32 = 4x4 m16n8k16 frags, 4 chunks of K=64.
__global__ __launch_bounds__(256, 2) void proj_kernel(
    const float* __restrict__ x,
    const float* __restrict__ gamma, const float* __restrict__ beta,
    const float* __restrict__ rmean, const float* __restrict__ rvar)
{
    extern __shared__ __align__(16) char dsm[];
    float (*Bs)[64][132] = reinterpret_cast<float(*)[64][132]>(dsm);
    float* sinv = reinterpret_cast<float*>(dsm + 2 * BS_STRIDE);
    float* sbz  = sinv + 128;

    const int tid  = threadIdx.x;
    const int warp = tid >> 5;
    const int lane = tid & 31;
    const int o0   = blockIdx.x * 128;
    const int pg0  = blockIdx.y * 128;
    const int b    = pg0 / HW;               // tile never crosses batch
    const int pp0  = pg0 - b * HW;
    const float* xb = x + (size_t)b * (Cc * HW);

    if (tid < 128) {
        int og = o0 + tid;
        float iv = gamma[og] * rsqrtf(rvar[og] + 1e-5f);
        sinv[tid] = iv;
        sbz[tid]  = beta[og] - rmean[og] * iv;
    }

    const int g  = lane >> 2;
    const int l3 = lane & 3;
    const int wm = (warp >> 2) * 64;
    const int wn = (warp & 3) * 32;
    const int ot = blockIdx.x;
    const int mtb = (warp >> 2) * 4;         // unused rows handled by mi*? see a-frag calc

    const uint32_t bs0 = smem_u32(&Bs[0][0][0]);
    #define ISSUE_B(cc, buf) do {                                                  \
        const float* _src = xb + (size_t)((cc) * 64) * HW + pp0;                   \
        _Pragma("unroll")                                                          \
        for (int l = 0; l < 8; l++) {                                              \
            int idx = tid + l * 256;                                               \
            int r = idx >> 5, c16 = idx & 31;                                      \
            uint32_t d = bs0 + (buf) * BS_STRIDE + r * 528 + c16 * 16;             \
            CP_ASYNC16(d, _src + (size_t)r * HW + c16 * 4);                        \
        }                                                                          \
        CP_COMMIT();                                                               \
    } while (0)

    float acc[4][4][4];
#pragma unroll
    for (int mi = 0; mi < 4; mi++)
#pragma unroll
        for (int ni = 0; ni < 4; ni++)
#pragma unroll
            for (int r = 0; r < 4; r++) acc[mi][ni][r] = 0.f;

    ISSUE_B(0, 0);

#pragma unroll 1
    for (int c = 0; c < 4; c++) {
        const int buf = c & 1;
        CP_WAIT0();          // B(c) landed (this thread's copies)
        __syncthreads();     // CTA-wide: B(c) visible; all reads of buf^1 (iter c-1) done
        if (c + 1 < 4) ISSUE_B(c + 1, buf ^ 1);

#pragma unroll
        for (int s = 0; s < 4; s++) {        // 4 x k16 steps per 64-chunk
            const int k = s * 16 + 2 * l3;
            const int ks16 = c * 4 + s;      // global k16-step 0..15
            uint32_t a[4][4], bf[4][2];
            const uint4* wf =
                &g_wfrag[((ot * 16 + ks16) * 8 + ((wm >> 4) /*0 or 4*/)) * 32 + lane];
#pragma unroll
            for (int mi = 0; mi < 4; mi++) {
                uint4 av = wf[mi * 32];
                a[mi][0] = av.x; a[mi][1] = av.y; a[mi][2] = av.z; a[mi][3] = av.w;
            }
#pragma unroll
            for (int ni = 0; ni < 4; ni++) {
                int p = wn + ni * 8 + g;
                __half2 h0 = __floats2half2_rn(Bs[buf][k][p],     Bs[buf][k + 1][p]);
                __half2 h1 = __floats2half2_rn(Bs[buf][k + 8][p], Bs[buf][k + 9][p]);
                bf[ni][0] = *reinterpret_cast<uint32_t*>(&h0);
                bf[ni][1] = *reinterpret_cast<uint32_t*>(&h1);
            }
#pragma unroll
            for (int mi = 0; mi < 4; mi++)
#pragma unroll
                for (int ni = 0; ni < 4; ni++)
                    mma_f16(acc[mi][ni], a[mi], bf[ni]);
        }
    }
    #undef ISSUE_B

    // epilogue: BN + ReLU + scatter into j-split fragment layouts (identical to R15)
    int winv[4][2], nn[4][2];
#pragma unroll
    for (int ni = 0; ni < 4; ni++)
#pragma unroll
        for (int e = 0; e < 2; e++) {
            int pin = pp0 + wn + ni * 8 + 2 * l3 + e;
            int row = pin / 192;
            int col = pin - row * 192;
            winv[ni][e] = b * 576 + (row >> 3) * 24 + (col >> 3);
            nn[ni][e]   = ((row & 7) << 3) + (col & 7);
        }
#pragma unroll
    for (int mi = 0; mi < 4; mi++) {
#pragma unroll
        for (int rh = 0; rh < 2; rh++) {
            int ol = wm + mi * 16 + g + rh * 8;
            int o  = o0 + ol;
            float iv = sinv[ol], bz = sbz[ol];
            int qkv  = o >> 8;
            int head = (o >> 4) & 15;
            int d    = o & 15;
            int dl = (d >> 1) & 3, de = d & 1, dh = d >> 3;
            __half* gb = g_scratch + (size_t)qkv * QKV_STRIDE + head * 1024;
#pragma unroll
            for (int ni = 0; ni < 4; ni++)
#pragma unroll
                for (int e = 0; e < 2; e++) {
                    float t = acc[mi][ni][rh * 2 + e] * iv + bz;
                    t = t > 0.f ? t : 0.f;
                    int n = nn[ni][e];
                    int off;
                    if (qkv == 0) {
                        t *= 0.36067376f;   // 0.25 * log2(e) folded into q
                        off = (n >> 4) * 256 + (((n >> 3) & 1) + 2 * dh) * 64
                            + ((((n & 7) << 2) | dl) << 1) + de;
                    } else {
                        off = (n >> 3) * 128 + dh * 64
                            + ((((n & 7) << 2) | dl) << 1) + de;
                    }
                    gb[(size_t)winv[ni][e] * 16384 + off] = __float2half_rn(t);
                }
        }
    }
}

// ---------------- attention: unchanged from R15 -----------------------------------------
__global__ __launch_bounds__(256, 4) void attn_kernel(
    const float* __restrict__ rel_table,
    float* __restrict__ out_attn, float* __restrict__ out_avg)
{
    __shared__ float biasl[232];

    const int tid  = threadIdx.x;
    const int w    = tid >> 5;
    const int lane = tid & 31;
    const int head = blockIdx.x & 15;
    const int wp   = blockIdx.x >> 4;

    if (tid < 225) biasl[tid] = rel_table[tid * 16 + head] * 1.4426950408f;
    __syncthreads();

    const int win   = wp * 2 + (w >> 2);
    const int slice = w & 3;
    const __half* qb = g_scratch + (size_t)(win * 16 + head) * 1024;
    const __half* kb = qb + QKV_STRIDE;

    const __half* qs = qb + slice * 256;
    uint32_t a[4];
    a[0] = *reinterpret_cast<const uint32_t*>(qs + 0 * 64 + lane * 2);
    a[1] = *reinterpret_cast<const uint32_t*>(qs + 1 * 64 + lane * 2);
    a[2] = *reinterpret_cast<const uint32_t*>(qs + 2 * 64 + lane * 2);
    a[3] = *reinterpret_cast<const uint32_t*>(qs + 3 * 64 + lane * 2);

    float acc[8][4];
#pragma unroll
    for (int ni = 0; ni < 8; ni++) {
#pragma unroll
        for (int r = 0; r < 4; r++) acc[ni][r] = 0.f;
        uint32_t bf[2];
        bf[0] = *reinterpret_cast<const uint32_t*>(kb + ni * 128 + lane * 2);
        bf[1] = *reinterpret_cast<const uint32_t*>(kb + ni * 128 + 64 + lane * 2);
        mma_f16(acc[ni], a, bf);
    }

    const int g  = lane >> 2;
    const int l3 = lane & 3;
    const int X0 = g - 2 * l3 + 7;
#pragma unroll
    for (int ni = 0; ni < 8; ni++) {
        const float* r0 = &biasl[(slice * 2 - ni + 7) * 15];
        acc[ni][0] += r0[X0];
        acc[ni][1] += r0[X0 - 1];
        acc[ni][2] += r0[15 + X0];
        acc[ni][3] += r0[15 + X0 - 1];
    }

#pragma unroll
    for (int ni = 0; ni < 8; ni++)
#pragma unroll
        for (int e = 0; e < 2; e++) {
            float s = acc[ni][e] + acc[ni][2 + e];
            s += __shfl_xor_sync(0xffffffffu, s, 4);
            s += __shfl_xor_sync(0xffffffffu, s, 8);
            s += __shfl_xor_sync(0xffffffffu, s, 16);
            if (g == 0)
                atomicAdd(&out_avg[win * 64 + ni * 8 + 2 * l3 + e],
                          s * 6.7690154e-4f);   // ln2/1024
        }

#pragma unroll
    for (int h = 0; h < 2; h++) {
        float mx = fmaxf(acc[0][2*h], acc[0][2*h+1]);
#pragma unroll
        for (int ni = 1; ni < 8; ni++)
            mx = fmaxf(mx, fmaxf(acc[ni][2*h], acc[ni][2*h+1]));
        mx = fmaxf(mx, __shfl_xor_sync(0xffffffffu, mx, 1));
        mx = fmaxf(mx, __shfl_xor_sync(0xffffffffu, mx, 2));
        float sum = 0.f;
#pragma unroll
        for (int ni = 0; ni < 8; ni++) {
            acc[ni][2*h]   = ex2f(acc[ni][2*h]   - mx);
            acc[ni][2*h+1] = ex2f(acc[ni][2*h+1] - mx);
            sum += acc[ni][2*h] + acc[ni][2*h+1];
        }
        sum += __shfl_xor_sync(0xffffffffu, sum, 1);
        sum += __shfl_xor_sync(0xffffffffu, sum, 2);
        float rinv = __frcp_rn(sum);
#pragma unroll
        for (int ni = 0; ni < 8; ni++) {
            acc[ni][2*h]   *= rinv;
            acc[ni][2*h+1] *= rinv;
        }
    }

    float* ob = out_attn + ((size_t)(win * 16 + head) * 64 + slice * 16 + g) * 64 + 2 * l3;
#pragma unroll
    for (int ni = 0; ni < 8; ni++) {
        *reinterpret_cast<float2*>(ob + ni * 8)          = make_float2(acc[ni][0], acc[ni][1]);
        *reinterpret_cast<float2*>(ob + 8 * 64 + ni * 8) = make_float2(acc[ni][2], acc[ni][3]);
    }
}

extern "C" void kernel_launch(void* const* d_in, const int* in_sizes, int n_in,
                              void* d_out, int out_size) {
    const float* x     = (const float*)d_in[0];
    const float* w     = (const float*)d_in[1];
    const float* gamma = (const float*)d_in[2];
    const float* beta  = (const float*)d_in[3];
    const float* rmean = (const float*)d_in[4];
    const float* rvar  = (const float*)d_in[5];
    const float* rel   = (const float*)d_in[6];
    float* out     = (float*)d_out;
    float* out_avg = out + ATTN_ELEMS;

    static bool attr_set = false;
    if (!attr_set) {
        cudaFuncSetAttribute(proj_kernel, cudaFuncAttributeMaxDynamicSharedMemorySize,
                             PROJ_SMEM);
        attr_set = true;
    }
    cudaMemsetAsync(out_avg, 0, AVG_ELEMS * sizeof(float));
    wconv_kernel<<<64, 256>>>(w);
    proj_kernel<<<dim3(4, 576), 256, PROJ_SMEM>>>(x, gamma, beta, rmean, rvar);
    attn_kernel<<<9216, 256>>>(rel, out, out_avg);
}